// round 5
// baseline (speedup 1.0000x reference)
#include <cuda_runtime.h>
#include <cuda_fp16.h>

#define N_USERS 100000
#define N_ITEMS 50000
#define N_NODES 150000  // N_USERS + N_ITEMS
#define EMBED   64
#define NNZ     4000000
#define BATCH   4096
#define ROW2    32            // EMBED floats = 32 float2 ; also 32 half2
#define ROW4    16
#define TOTAL2  (N_NODES * ROW2)

// ---------------------------------------------------------------------------
// Device-global scratch
// ---------------------------------------------------------------------------
__device__ __half g_E0h[N_NODES * EMBED];
__device__ __half g_E1h[N_NODES * EMBED];
__device__ float  g_acc[N_NODES * EMBED];

__device__ int  g_cnt[N_NODES];    // degree histogram
__device__ int  g_off[N_NODES];    // exclusive offsets
__device__ int  g_cur[N_NODES];    // scatter cursors
__device__ int  g_bsum[256];       // per-segment sums (147 used)
__device__ int2 g_edges[NNZ];      // packed (col, a) sorted by row — 32 MB dense

// ---------------------------------------------------------------------------
// init + hist fused: acc = concat(eu, ei); E0h = fp16(acc); cnt histogram
// (g_cnt zeroed by preceding memsetAsync)
// ---------------------------------------------------------------------------
__global__ void lgcn_init_hist(const float2* __restrict__ eu,
                               const float2* __restrict__ ei,
                               const int* __restrict__ row) {
    float2* acc2 = reinterpret_cast<float2*>(g_acc);
    half2*  E0h2 = reinterpret_cast<half2*>(g_E0h);
    const int stride = gridDim.x * blockDim.x;
    const int gid = blockIdx.x * blockDim.x + threadIdx.x;
    const int user2 = N_USERS * ROW2;
    for (int i = gid; i < TOTAL2; i += stride) {
        float2 v = (i < user2) ? eu[i] : ei[i - user2];
        acc2[i] = v;
        E0h2[i] = __float22half2_rn(v);
    }
    for (int e = gid; e < NNZ; e += stride)
        atomicAdd(&g_cnt[__ldg(row + e)], 1);        // no return -> RED
}

// ---------------------------------------------------------------------------
// CSR build: per-segment scan -> (base computed in-place) -> scatter
// ---------------------------------------------------------------------------
#define SCAN_B 1024
__global__ void k_scan_local() {
    __shared__ int s[SCAN_B];
    const int tid = threadIdx.x;
    const int i = blockIdx.x * SCAN_B + tid;
    int v = (i < N_NODES) ? g_cnt[i] : 0;
    s[tid] = v;
    __syncthreads();
    #pragma unroll
    for (int d = 1; d < SCAN_B; d <<= 1) {
        int t = (tid >= d) ? s[tid - d] : 0;
        __syncthreads();
        s[tid] += t;
        __syncthreads();
    }
    if (i < N_NODES) g_off[i] = s[tid] - v;          // exclusive within segment
    if (tid == SCAN_B - 1) g_bsum[blockIdx.x] = s[tid];
}

// one block per SCAN_B segment; each block sums bsum[0..blockIdx) itself
__global__ void k_scan_add() {
    __shared__ int base_s;
    const int tid = threadIdx.x;
    if (tid == 0) base_s = 0;
    __syncthreads();
    int partial = 0;
    for (int k = tid; k < blockIdx.x; k += blockDim.x) partial += g_bsum[k];
    // warp-reduce then atomic into shared
    #pragma unroll
    for (int d = 16; d; d >>= 1) partial += __shfl_down_sync(0xffffffffu, partial, d);
    if ((tid & 31) == 0 && partial) atomicAdd(&base_s, partial);
    __syncthreads();
    const int base = base_s;
    const int i = blockIdx.x * SCAN_B + tid;        // blockDim == SCAN_B
    if (i < N_NODES) {
        int o = g_off[i] + base;
        g_off[i] = o;
        g_cur[i] = o;
    }
}

__global__ void k_scatter(const int* __restrict__ row,
                          const int* __restrict__ col,
                          const float* __restrict__ a) {
    const int stride = gridDim.x * blockDim.x;
    for (int e = blockIdx.x * blockDim.x + threadIdx.x; e < NNZ; e += stride) {
        const int r = __ldg(row + e);
        int p = atomicAdd(&g_cur[r], 1);
        int2 pk;
        pk.x = __ldg(col + e);
        pk.y = __float_as_int(__ldg(a + e));
        g_edges[p] = pk;
    }
}

// ---------------------------------------------------------------------------
// CSR SpMM with warp-cooperative edge staging.
// One warp per node. Per 32-edge chunk: lanes coalesce-load edges into smem
// (2 wavefronts for 32 edges, off the gather critical path), then the gather
// loop issues independent LDGs back-to-back (only carried dep is the sum).
//   dst[n] = fp16( sum_j a[j] * src[col[j]] );  acc[n] += sum (fp32)
// ---------------------------------------------------------------------------
#define SPMM_T 256
#define WPB    (SPMM_T / 32)
template<bool WRITE_DST>
__global__ void lgcn_csr(const half2* __restrict__ src,
                         half2* __restrict__ dst) {
    __shared__ int2 se[WPB][32];
    const int warp = (blockIdx.x * blockDim.x + threadIdx.x) >> 5;
    const int wloc = threadIdx.x >> 5;
    const int lane = threadIdx.x & 31;
    if (warp >= N_NODES) return;
    const int s = __ldg(&g_off[warp]);
    const int n = __ldg(&g_cnt[warp]);

    float2 sum = make_float2(0.f, 0.f);
    for (int base = 0; base < n; base += 32) {
        const int m = min(32, n - base);
        if (lane < m) se[wloc][lane] = __ldg(g_edges + s + base + lane);
        __syncwarp();
        #pragma unroll 8
        for (int j = 0; j < m; j++) {
            const int2  e  = se[wloc][j];            // LDS broadcast
            const float av = __int_as_float(e.y);
            float2 v = __half22float2(__ldg(src + (size_t)e.x * ROW2 + lane));
            sum.x += av * v.x;
            sum.y += av * v.y;
        }
        __syncwarp();
    }
    const size_t o = (size_t)warp * ROW2 + lane;
    if (WRITE_DST) dst[o] = __float22half2_rn(sum);
    float2* acc2 = reinterpret_cast<float2*>(g_acc);
    float2 a0 = acc2[o];
    acc2[o] = make_float2(a0.x + sum.x, a0.y + sum.y);
}

// ---------------------------------------------------------------------------
// gather: out = [acc[user] ; acc[N_USERS+pos] ; acc[N_USERS+neg]] * 0.25
// ---------------------------------------------------------------------------
__global__ void lgcn_gather(const int* __restrict__ bu,
                            const int* __restrict__ bp,
                            const int* __restrict__ bn,
                            float4* __restrict__ out) {
    const float4* acc = reinterpret_cast<const float4*>(g_acc);
    const int tid  = blockIdx.x * blockDim.x + threadIdx.x;
    const int lane = tid & 15;
    const int r    = tid >> 4;
    if (r >= 3 * BATCH) return;
    const int which = r / BATCH;
    const int b     = r - which * BATCH;
    int node;
    if (which == 0)      node = __ldg(bu + b);
    else if (which == 1) node = N_USERS + __ldg(bp + b);
    else                 node = N_USERS + __ldg(bn + b);
    float4 v = acc[(size_t)node * ROW4 + lane];
    const float sc = 0.25f;   // 1/(N_LAYERS+1)
    out[(size_t)r * ROW4 + lane] = make_float4(v.x * sc, v.y * sc, v.z * sc, v.w * sc);
}

// ---------------------------------------------------------------------------
// launch
// ---------------------------------------------------------------------------
extern "C" void kernel_launch(void* const* d_in, const int* in_sizes, int n_in,
                              void* d_out, int out_size) {
    const int*   batch_user = (const int*)  d_in[0];
    const int*   batch_pos  = (const int*)  d_in[1];
    const int*   batch_neg  = (const int*)  d_in[2];
    const float* embed_user = (const float*)d_in[3];
    const float* embed_item = (const float*)d_in[4];
    const int*   row_idx    = (const int*)  d_in[5];
    const int*   col_idx    = (const int*)  d_in[6];
    const float* a_vals     = (const float*)d_in[7];
    float* out = (float*)d_out;

    half2* E0 = nullptr;
    half2* E1 = nullptr;
    void*  cntp = nullptr;
    cudaGetSymbolAddress((void**)&E0, g_E0h);
    cudaGetSymbolAddress((void**)&E1, g_E1h);
    cudaGetSymbolAddress(&cntp, g_cnt);

    const int T = 256;
    const int initBlocks   = 2048;
    const int edgeBlocks   = 148 * 8;
    const int scanBlocks   = (N_NODES + SCAN_B - 1) / SCAN_B;     // 147
    const int csrBlocks    = (N_NODES * 32 + SPMM_T - 1) / SPMM_T;
    const int gatherBlocks = (3 * BATCH * 16 + T - 1) / T;

    cudaMemsetAsync(cntp, 0, N_NODES * sizeof(int));
    lgcn_init_hist<<<initBlocks, T>>>((const float2*)embed_user,
                                      (const float2*)embed_item, row_idx);

    k_scan_local<<<scanBlocks, SCAN_B>>>();
    k_scan_add<<<scanBlocks, SCAN_B>>>();
    k_scatter<<<edgeBlocks, T>>>(row_idx, col_idx, a_vals);

    // 3 propagation layers, acc fused
    lgcn_csr<true ><<<csrBlocks, SPMM_T>>>(E0, E1);   // layer 1: E0 -> E1
    lgcn_csr<true ><<<csrBlocks, SPMM_T>>>(E1, E0);   // layer 2: E1 -> E0
    lgcn_csr<false><<<csrBlocks, SPMM_T>>>(E0, E1);   // layer 3: acc only

    lgcn_gather<<<gatherBlocks, T>>>(batch_user, batch_pos, batch_neg,
                                     (float4*)out);
}

// round 6
// speedup vs baseline: 1.0880x; 1.0880x over previous
#include <cuda_runtime.h>
#include <cuda_fp16.h>

#define N_USERS 100000
#define N_ITEMS 50000
#define N_NODES 150000  // N_USERS + N_ITEMS
#define EMBED   64
#define NNZ     4000000
#define BATCH   4096
#define ROW2    32            // EMBED floats = 32 float2
#define ROWU2   16            // EMBED halves = 16 uint2 (8B chunks)
#define TOTAL2  (N_NODES * ROW2)

// ---------------------------------------------------------------------------
// Device-global scratch. Four fp16 layer tables (no fp32 accumulator: the
// final gather sums E0..E3 for just the 12k requested rows).
// ---------------------------------------------------------------------------
__device__ __half g_E0h[N_NODES * EMBED];
__device__ __half g_E1h[N_NODES * EMBED];
__device__ __half g_E2h[N_NODES * EMBED];
__device__ __half g_E3h[N_NODES * EMBED];

__device__ int  g_cnt[N_NODES];    // degree histogram
__device__ int  g_off[N_NODES];    // exclusive offsets
__device__ int  g_rank[NNZ];       // per-edge rank within its row
__device__ int  g_bsum[256];       // per-segment sums (147 used)
__device__ int2 g_edges[NNZ];      // packed (col, a) sorted by row — 32 MB dense

// ---------------------------------------------------------------------------
// init + hist fused: E0h = fp16(concat(eu, ei));
// rank[e] = cnt[row[e]]++  (atomic-return doubles as counting-sort rank)
// ---------------------------------------------------------------------------
__global__ void lgcn_init_hist(const float2* __restrict__ eu,
                               const float2* __restrict__ ei,
                               const int* __restrict__ row) {
    half2* E0h2 = reinterpret_cast<half2*>(g_E0h);
    const int stride = gridDim.x * blockDim.x;
    const int gid = blockIdx.x * blockDim.x + threadIdx.x;
    const int user2 = N_USERS * ROW2;
    for (int i = gid; i < TOTAL2; i += stride) {
        float2 v = (i < user2) ? eu[i] : ei[i - user2];
        E0h2[i] = __float22half2_rn(v);
    }
    for (int e = gid; e < NNZ; e += stride)
        g_rank[e] = atomicAdd(&g_cnt[__ldg(row + e)], 1);
}

// ---------------------------------------------------------------------------
// CSR offsets: per-segment scan, then each block derives its own base
// ---------------------------------------------------------------------------
#define SCAN_B 1024
__global__ void k_scan_local() {
    __shared__ int s[SCAN_B];
    const int tid = threadIdx.x;
    const int i = blockIdx.x * SCAN_B + tid;
    int v = (i < N_NODES) ? g_cnt[i] : 0;
    s[tid] = v;
    __syncthreads();
    #pragma unroll
    for (int d = 1; d < SCAN_B; d <<= 1) {
        int t = (tid >= d) ? s[tid - d] : 0;
        __syncthreads();
        s[tid] += t;
        __syncthreads();
    }
    if (i < N_NODES) g_off[i] = s[tid] - v;          // exclusive within segment
    if (tid == SCAN_B - 1) g_bsum[blockIdx.x] = s[tid];
}

__global__ void k_scan_add() {
    __shared__ int base_s;
    const int tid = threadIdx.x;
    if (tid == 0) base_s = 0;
    __syncthreads();
    int partial = 0;
    for (int k = tid; k < blockIdx.x; k += blockDim.x) partial += g_bsum[k];
    #pragma unroll
    for (int d = 16; d; d >>= 1) partial += __shfl_down_sync(0xffffffffu, partial, d);
    if ((tid & 31) == 0 && partial) atomicAdd(&base_s, partial);
    __syncthreads();
    const int i = blockIdx.x * SCAN_B + tid;        // blockDim == SCAN_B
    if (i < N_NODES) g_off[i] += base_s;
}

// ---------------------------------------------------------------------------
// scatter, atomic-free: p = off[row[e]] + rank[e]
// ---------------------------------------------------------------------------
__global__ void k_scatter(const int* __restrict__ row,
                          const int* __restrict__ col,
                          const float* __restrict__ a) {
    const int stride = gridDim.x * blockDim.x;
    for (int e = blockIdx.x * blockDim.x + threadIdx.x; e < NNZ; e += stride) {
        const int r = __ldg(row + e);
        const int p = __ldg(&g_off[r]) + __ldg(&g_rank[e]);
        int2 pk;
        pk.x = __ldg(col + e);
        pk.y = __float_as_int(__ldg(a + e));
        g_edges[p] = pk;
    }
}

// ---------------------------------------------------------------------------
// CSR SpMM, fp16 in/out, fp32 math. One warp per node, TWO edges per
// iteration: half-warp h handles edge base+h, 16 lanes × 8B cover the row.
// Halves gather-LDG instruction count and doubles per-warp MLP.
// ---------------------------------------------------------------------------
#define SPMM_T 256
__global__ void lgcn_csr(const uint2* __restrict__ src,
                         uint2* __restrict__ dst) {
    const int warp = (blockIdx.x * SPMM_T + threadIdx.x) >> 5;
    const int lane = threadIdx.x & 31;
    if (warp >= N_NODES) return;
    const int s    = __ldg(&g_off[warp]);
    const int n    = __ldg(&g_cnt[warp]);
    const int half = lane >> 4;          // 0 or 1: which edge of the pair
    const int l16  = lane & 15;          // 8B chunk within the 128B row

    float4 sum = make_float4(0.f, 0.f, 0.f, 0.f);
    #pragma unroll 4
    for (int base = 0; base < n; base += 2) {
        const int idx = base + half;
        const int2 e = (idx < n) ? __ldg(g_edges + s + idx) : make_int2(0, 0);
        const float av = __int_as_float(e.y);
        uint2 h = __ldg(src + ((size_t)e.x << 4) + l16);
        float2 v0 = __half22float2(*reinterpret_cast<half2*>(&h.x));
        float2 v1 = __half22float2(*reinterpret_cast<half2*>(&h.y));
        sum.x += av * v0.x;
        sum.y += av * v0.y;
        sum.z += av * v1.x;
        sum.w += av * v1.y;
    }
    // combine the two half-warps
    sum.x += __shfl_xor_sync(0xffffffffu, sum.x, 16);
    sum.y += __shfl_xor_sync(0xffffffffu, sum.y, 16);
    sum.z += __shfl_xor_sync(0xffffffffu, sum.z, 16);
    sum.w += __shfl_xor_sync(0xffffffffu, sum.w, 16);
    if (lane < 16) {
        half2 p0 = __floats2half2_rn(sum.x, sum.y);
        half2 p1 = __floats2half2_rn(sum.z, sum.w);
        uint2 o;
        o.x = *reinterpret_cast<unsigned*>(&p0);
        o.y = *reinterpret_cast<unsigned*>(&p1);
        dst[((size_t)warp << 4) + l16] = o;
    }
}

// ---------------------------------------------------------------------------
// gather: out[r] = (E0+E1+E2+E3)[node] * 0.25, fp32 out.
// 16 threads per row; each thread sums one 8B chunk across the 4 tables.
// ---------------------------------------------------------------------------
__global__ void lgcn_gather(const int* __restrict__ bu,
                            const int* __restrict__ bp,
                            const int* __restrict__ bn,
                            float4* __restrict__ out) {
    const int tid  = blockIdx.x * blockDim.x + threadIdx.x;
    const int l16  = tid & 15;
    const int r    = tid >> 4;
    if (r >= 3 * BATCH) return;
    const int which = r / BATCH;
    const int b     = r - which * BATCH;
    int node;
    if (which == 0)      node = __ldg(bu + b);
    else if (which == 1) node = N_USERS + __ldg(bp + b);
    else                 node = N_USERS + __ldg(bn + b);

    const size_t o = ((size_t)node << 4) + l16;
    const uint2* tabs[4] = {
        reinterpret_cast<const uint2*>(g_E0h),
        reinterpret_cast<const uint2*>(g_E1h),
        reinterpret_cast<const uint2*>(g_E2h),
        reinterpret_cast<const uint2*>(g_E3h)
    };
    float4 s = make_float4(0.f, 0.f, 0.f, 0.f);
    #pragma unroll
    for (int t = 0; t < 4; t++) {
        uint2 h = __ldg(tabs[t] + o);
        float2 v0 = __half22float2(*reinterpret_cast<half2*>(&h.x));
        float2 v1 = __half22float2(*reinterpret_cast<half2*>(&h.y));
        s.x += v0.x; s.y += v0.y; s.z += v1.x; s.w += v1.y;
    }
    const float sc = 0.25f;   // 1/(N_LAYERS+1)
    out[((size_t)r << 4) + l16] =
        make_float4(s.x * sc, s.y * sc, s.z * sc, s.w * sc);
}

// ---------------------------------------------------------------------------
// launch
// ---------------------------------------------------------------------------
extern "C" void kernel_launch(void* const* d_in, const int* in_sizes, int n_in,
                              void* d_out, int out_size) {
    const int*   batch_user = (const int*)  d_in[0];
    const int*   batch_pos  = (const int*)  d_in[1];
    const int*   batch_neg  = (const int*)  d_in[2];
    const float* embed_user = (const float*)d_in[3];
    const float* embed_item = (const float*)d_in[4];
    const int*   row_idx    = (const int*)  d_in[5];
    const int*   col_idx    = (const int*)  d_in[6];
    const float* a_vals     = (const float*)d_in[7];
    float* out = (float*)d_out;

    uint2 *E0, *E1, *E2, *E3;
    void* cntp = nullptr;
    cudaGetSymbolAddress((void**)&E0, g_E0h);
    cudaGetSymbolAddress((void**)&E1, g_E1h);
    cudaGetSymbolAddress((void**)&E2, g_E2h);
    cudaGetSymbolAddress((void**)&E3, g_E3h);
    cudaGetSymbolAddress(&cntp, g_cnt);

    const int T = 256;
    const int initBlocks   = 2048;
    const int edgeBlocks   = 148 * 8;
    const int scanBlocks   = (N_NODES + SCAN_B - 1) / SCAN_B;     // 147
    const int csrBlocks    = (N_NODES * 32 + SPMM_T - 1) / SPMM_T;
    const int gatherBlocks = (3 * BATCH * 16 + T - 1) / T;

    cudaMemsetAsync(cntp, 0, N_NODES * sizeof(int));
    lgcn_init_hist<<<initBlocks, T>>>((const float2*)embed_user,
                                      (const float2*)embed_item, row_idx);

    k_scan_local<<<scanBlocks, SCAN_B>>>();
    k_scan_add<<<scanBlocks, SCAN_B>>>();
    k_scatter<<<edgeBlocks, T>>>(row_idx, col_idx, a_vals);

    // 3 propagation layers into separate tables
    lgcn_csr<<<csrBlocks, SPMM_T>>>(E0, E1);
    lgcn_csr<<<csrBlocks, SPMM_T>>>(E1, E2);
    lgcn_csr<<<csrBlocks, SPMM_T>>>(E2, E3);

    lgcn_gather<<<gatherBlocks, T>>>(batch_user, batch_pos, batch_neg,
                                     (float4*)out);
}

// round 7
// speedup vs baseline: 1.4949x; 1.3740x over previous
#include <cuda_runtime.h>
#include <cuda_fp16.h>

#define N_USERS 100000
#define N_ITEMS 50000
#define N_NODES 150000  // N_USERS + N_ITEMS
#define EMBED   64
#define NNZ     4000000
#define BATCH   4096
#define ROW2    32            // EMBED floats = 32 float2
#define TOTAL2  (N_NODES * ROW2)

// ---------------------------------------------------------------------------
// Device-global scratch. Three fp16 layer tables; layer 3 is computed only
// at the 12k batch rows, fused into the final gather (fp32 path).
// ---------------------------------------------------------------------------
__device__ __half g_E0h[N_NODES * EMBED];
__device__ __half g_E1h[N_NODES * EMBED];
__device__ __half g_E2h[N_NODES * EMBED];

__device__ int  g_cnt[N_NODES];    // degree histogram
__device__ int  g_off[N_NODES];    // exclusive offsets
__device__ int  g_rank[NNZ];       // per-edge rank within its row
__device__ int  g_bsum[256];       // per-segment sums (147 used)
__device__ int2 g_edges[NNZ];      // packed (col, a) sorted by row — 32 MB

// ---------------------------------------------------------------------------
// init + hist fused: E0h = fp16(concat(eu, ei));
// rank[e] = cnt[row[e]]++  (atomic-return doubles as counting-sort rank)
// ---------------------------------------------------------------------------
__global__ void lgcn_init_hist(const float2* __restrict__ eu,
                               const float2* __restrict__ ei,
                               const int* __restrict__ row) {
    half2* E0h2 = reinterpret_cast<half2*>(g_E0h);
    const int stride = gridDim.x * blockDim.x;
    const int gid = blockIdx.x * blockDim.x + threadIdx.x;
    const int user2 = N_USERS * ROW2;
    for (int i = gid; i < TOTAL2; i += stride) {
        float2 v = (i < user2) ? eu[i] : ei[i - user2];
        E0h2[i] = __float22half2_rn(v);
    }
    for (int e = gid; e < NNZ; e += stride)
        g_rank[e] = atomicAdd(&g_cnt[__ldg(row + e)], 1);
}

// ---------------------------------------------------------------------------
// CSR offsets: per-segment scan, then each block derives its own base
// ---------------------------------------------------------------------------
#define SCAN_B 1024
__global__ void k_scan_local() {
    __shared__ int s[SCAN_B];
    const int tid = threadIdx.x;
    const int i = blockIdx.x * SCAN_B + tid;
    int v = (i < N_NODES) ? g_cnt[i] : 0;
    s[tid] = v;
    __syncthreads();
    #pragma unroll
    for (int d = 1; d < SCAN_B; d <<= 1) {
        int t = (tid >= d) ? s[tid - d] : 0;
        __syncthreads();
        s[tid] += t;
        __syncthreads();
    }
    if (i < N_NODES) g_off[i] = s[tid] - v;          // exclusive within segment
    if (tid == SCAN_B - 1) g_bsum[blockIdx.x] = s[tid];
}

__global__ void k_scan_add() {
    __shared__ int base_s;
    const int tid = threadIdx.x;
    if (tid == 0) base_s = 0;
    __syncthreads();
    int partial = 0;
    for (int k = tid; k < blockIdx.x; k += blockDim.x) partial += g_bsum[k];
    #pragma unroll
    for (int d = 16; d; d >>= 1) partial += __shfl_down_sync(0xffffffffu, partial, d);
    if ((tid & 31) == 0 && partial) atomicAdd(&base_s, partial);
    __syncthreads();
    const int i = blockIdx.x * SCAN_B + tid;        // blockDim == SCAN_B
    if (i < N_NODES) g_off[i] += base_s;
}

// ---------------------------------------------------------------------------
// scatter, atomic-free: p = off[row[e]] + rank[e]
// ---------------------------------------------------------------------------
__global__ void k_scatter(const int* __restrict__ row,
                          const int* __restrict__ col,
                          const float* __restrict__ a) {
    const int stride = gridDim.x * blockDim.x;
    for (int e = blockIdx.x * blockDim.x + threadIdx.x; e < NNZ; e += stride) {
        const int r = __ldg(row + e);
        const int p = __ldg(&g_off[r]) + __ldg(&g_rank[e]);
        int2 pk;
        pk.x = __ldg(col + e);
        pk.y = __float_as_int(__ldg(a + e));
        g_edges[p] = pk;
    }
}

// ---------------------------------------------------------------------------
// CSR SpMM, fp16 in/out, fp32 math. One warp per node, FOUR edges per
// iteration: edge-group g = lane>>3 handles edge base+g; 8 lanes × 16B
// (uint4 = 8 halves) cover the 128B row. 4 independent gathers in flight
// per warp instruction. Reduction: 2 shfl_xor rounds.
// ---------------------------------------------------------------------------
#define SPMM_T 256
__global__ void lgcn_csr(const uint4* __restrict__ src,
                         uint4* __restrict__ dst) {
    const int warp = (blockIdx.x * SPMM_T + threadIdx.x) >> 5;
    const int lane = threadIdx.x & 31;
    if (warp >= N_NODES) return;
    const int s  = __ldg(&g_off[warp]);
    const int n  = __ldg(&g_cnt[warp]);
    const int eg = lane >> 3;          // 0..3: which edge of the quad
    const int l8 = lane & 7;           // 16B chunk within the 128B row

    float2 s0 = make_float2(0.f, 0.f), s1 = s0, s2 = s0, s3 = s0;
    #pragma unroll 2
    for (int base = 0; base < n; base += 4) {
        const int idx = base + eg;
        const int2 e = (idx < n) ? __ldg(g_edges + s + idx) : make_int2(0, 0);
        const float av = __int_as_float(e.y);
        uint4 h = __ldg(src + ((size_t)e.x << 3) + l8);
        float2 v0 = __half22float2(*reinterpret_cast<half2*>(&h.x));
        float2 v1 = __half22float2(*reinterpret_cast<half2*>(&h.y));
        float2 v2 = __half22float2(*reinterpret_cast<half2*>(&h.z));
        float2 v3 = __half22float2(*reinterpret_cast<half2*>(&h.w));
        s0.x += av * v0.x; s0.y += av * v0.y;
        s1.x += av * v1.x; s1.y += av * v1.y;
        s2.x += av * v2.x; s2.y += av * v2.y;
        s3.x += av * v3.x; s3.y += av * v3.y;
    }
    // combine the 4 edge-groups (lanes with equal l8)
    #pragma unroll
    for (int d = 8; d <= 16; d <<= 1) {
        s0.x += __shfl_xor_sync(0xffffffffu, s0.x, d);
        s0.y += __shfl_xor_sync(0xffffffffu, s0.y, d);
        s1.x += __shfl_xor_sync(0xffffffffu, s1.x, d);
        s1.y += __shfl_xor_sync(0xffffffffu, s1.y, d);
        s2.x += __shfl_xor_sync(0xffffffffu, s2.x, d);
        s2.y += __shfl_xor_sync(0xffffffffu, s2.y, d);
        s3.x += __shfl_xor_sync(0xffffffffu, s3.x, d);
        s3.y += __shfl_xor_sync(0xffffffffu, s3.y, d);
    }
    if (eg == 0) {
        half2 p0 = __floats2half2_rn(s0.x, s0.y);
        half2 p1 = __floats2half2_rn(s1.x, s1.y);
        half2 p2 = __floats2half2_rn(s2.x, s2.y);
        half2 p3 = __floats2half2_rn(s3.x, s3.y);
        uint4 o;
        o.x = *reinterpret_cast<unsigned*>(&p0);
        o.y = *reinterpret_cast<unsigned*>(&p1);
        o.z = *reinterpret_cast<unsigned*>(&p2);
        o.w = *reinterpret_cast<unsigned*>(&p3);
        dst[((size_t)warp << 3) + l8] = o;
    }
}

// ---------------------------------------------------------------------------
// Fused layer-3 + gather: one warp per output row.
//   e3 = sum_j a[j] * E2[col[j]]          (fp32, never quantized)
//   out[r] = 0.25 * ((E0+E1+E2)[node] + e3)
// ---------------------------------------------------------------------------
__global__ void lgcn_last(const int* __restrict__ bu,
                          const int* __restrict__ bp,
                          const int* __restrict__ bn,
                          float4* __restrict__ out) {
    const int warp = (blockIdx.x * blockDim.x + threadIdx.x) >> 5;
    const int lane = threadIdx.x & 31;
    if (warp >= 3 * BATCH) return;
    const int which = warp / BATCH;
    const int b     = warp - which * BATCH;
    int node;
    if (which == 0)      node = __ldg(bu + b);
    else if (which == 1) node = N_USERS + __ldg(bp + b);
    else                 node = N_USERS + __ldg(bn + b);

    const int s  = __ldg(&g_off[node]);
    const int n  = __ldg(&g_cnt[node]);
    const int eg = lane >> 3;
    const int l8 = lane & 7;

    const uint4* E2 = reinterpret_cast<const uint4*>(g_E2h);
    float2 s0 = make_float2(0.f, 0.f), s1 = s0, s2 = s0, s3 = s0;
    for (int base = 0; base < n; base += 4) {
        const int idx = base + eg;
        const int2 e = (idx < n) ? __ldg(g_edges + s + idx) : make_int2(0, 0);
        const float av = __int_as_float(e.y);
        uint4 h = __ldg(E2 + ((size_t)e.x << 3) + l8);
        float2 v0 = __half22float2(*reinterpret_cast<half2*>(&h.x));
        float2 v1 = __half22float2(*reinterpret_cast<half2*>(&h.y));
        float2 v2 = __half22float2(*reinterpret_cast<half2*>(&h.z));
        float2 v3 = __half22float2(*reinterpret_cast<half2*>(&h.w));
        s0.x += av * v0.x; s0.y += av * v0.y;
        s1.x += av * v1.x; s1.y += av * v1.y;
        s2.x += av * v2.x; s2.y += av * v2.y;
        s3.x += av * v3.x; s3.y += av * v3.y;
    }
    #pragma unroll
    for (int d = 8; d <= 16; d <<= 1) {
        s0.x += __shfl_xor_sync(0xffffffffu, s0.x, d);
        s0.y += __shfl_xor_sync(0xffffffffu, s0.y, d);
        s1.x += __shfl_xor_sync(0xffffffffu, s1.x, d);
        s1.y += __shfl_xor_sync(0xffffffffu, s1.y, d);
        s2.x += __shfl_xor_sync(0xffffffffu, s2.x, d);
        s2.y += __shfl_xor_sync(0xffffffffu, s2.y, d);
        s3.x += __shfl_xor_sync(0xffffffffu, s3.x, d);
        s3.y += __shfl_xor_sync(0xffffffffu, s3.y, d);
    }
    if (eg == 0) {
        // add E0+E1+E2 at node, scale, write fp32
        const size_t o = ((size_t)node << 3) + l8;
        const uint4* tabs[3] = {
            reinterpret_cast<const uint4*>(g_E0h),
            reinterpret_cast<const uint4*>(g_E1h),
            reinterpret_cast<const uint4*>(g_E2h)
        };
        #pragma unroll
        for (int t = 0; t < 3; t++) {
            uint4 h = __ldg(tabs[t] + o);
            float2 v0 = __half22float2(*reinterpret_cast<half2*>(&h.x));
            float2 v1 = __half22float2(*reinterpret_cast<half2*>(&h.y));
            float2 v2 = __half22float2(*reinterpret_cast<half2*>(&h.z));
            float2 v3 = __half22float2(*reinterpret_cast<half2*>(&h.w));
            s0.x += v0.x; s0.y += v0.y;
            s1.x += v1.x; s1.y += v1.y;
            s2.x += v2.x; s2.y += v2.y;
            s3.x += v3.x; s3.y += v3.y;
        }
        const float sc = 0.25f;   // 1/(N_LAYERS+1)
        float4* orow = out + ((size_t)warp << 4) + l8 * 2;
        orow[0] = make_float4(s0.x * sc, s0.y * sc, s1.x * sc, s1.y * sc);
        orow[1] = make_float4(s2.x * sc, s2.y * sc, s3.x * sc, s3.y * sc);
    }
}

// ---------------------------------------------------------------------------
// launch
// ---------------------------------------------------------------------------
extern "C" void kernel_launch(void* const* d_in, const int* in_sizes, int n_in,
                              void* d_out, int out_size) {
    const int*   batch_user = (const int*)  d_in[0];
    const int*   batch_pos  = (const int*)  d_in[1];
    const int*   batch_neg  = (const int*)  d_in[2];
    const float* embed_user = (const float*)d_in[3];
    const float* embed_item = (const float*)d_in[4];
    const int*   row_idx    = (const int*)  d_in[5];
    const int*   col_idx    = (const int*)  d_in[6];
    const float* a_vals     = (const float*)d_in[7];
    float* out = (float*)d_out;

    uint4 *E0, *E1, *E2;
    void* cntp = nullptr;
    cudaGetSymbolAddress((void**)&E0, g_E0h);
    cudaGetSymbolAddress((void**)&E1, g_E1h);
    cudaGetSymbolAddress((void**)&E2, g_E2h);
    cudaGetSymbolAddress(&cntp, g_cnt);

    const int T = 256;
    const int initBlocks = 2048;
    const int edgeBlocks = 148 * 8;
    const int scanBlocks = (N_NODES + SCAN_B - 1) / SCAN_B;     // 147
    const int csrBlocks  = (N_NODES * 32 + SPMM_T - 1) / SPMM_T;
    const int lastBlocks = (3 * BATCH * 32 + T - 1) / T;

    cudaMemsetAsync(cntp, 0, N_NODES * sizeof(int));
    lgcn_init_hist<<<initBlocks, T>>>((const float2*)embed_user,
                                      (const float2*)embed_item, row_idx);

    k_scan_local<<<scanBlocks, SCAN_B>>>();
    k_scan_add<<<scanBlocks, SCAN_B>>>();
    k_scatter<<<edgeBlocks, T>>>(row_idx, col_idx, a_vals);

    // layers 1 and 2 over all nodes
    lgcn_csr<<<csrBlocks, SPMM_T>>>(E0, E1);
    lgcn_csr<<<csrBlocks, SPMM_T>>>(E1, E2);

    // fused layer 3 + accumulate + gather over the 12k batch rows only
    lgcn_last<<<lastBlocks, T>>>(batch_user, batch_pos, batch_neg,
                                 (float4*)out);
}